// round 11
// baseline (speedup 1.0000x reference)
#include <cuda_runtime.h>
#include <math.h>

#define NN 6144
#define FIN 256
#define FOUT 64
#define ALPHA 0.2f
#define NNZ_MAX (1 << 20)
#define NWORDS (NN / 32)     // 192
#define DEGMAX 192
#define GEMM_BLOCKS (NN / 16)          // 384
#define CNT_BLOCKS  (NN / 8)           // 768
#define TOT_BLOCKS  (GEMM_BLOCKS + CNT_BLOCKS)

// ---------------- scratch (static device globals; zero-initialized) ----------
__device__ float    g_h[NN * FOUT];
__device__ float    g_Wh1[NN];
__device__ float    g_Wh2[NN];
__device__ int      g_row_cnt[NN];     // true out-degree
__device__ int      g_col_cnt[NN];     // true in-degree; zeroed by k_fused for next call
__device__ int      g_row_ptr[NN + 1]; // PADDED (x4-aligned) csr offsets
__device__ int      g_col_ptr[NN + 1]; // PADDED (x4-aligned) csc offsets
__device__ int      g_col_fill[NN];    // zeroed by k_fused for next call
__device__ int      g_csr_col[NNZ_MAX];
__device__ int      g_csc_row[NNZ_MAX];
__device__ unsigned g_bits[NN * NWORDS];   // PERMUTED word/bit order (see k_fill)
__device__ unsigned g_ticket;

// -------- 256-thread exclusive scan over 6144 ints, padding each to x4 -------
__device__ __forceinline__ void scan6144_pad(const int* __restrict__ in,
                                             int* __restrict__ out, int* s_w) {
    int tid = threadIdx.x, lane = tid & 31, warp = tid >> 5;
    int base = tid * 24;
    int t = 0;
    #pragma unroll
    for (int q = 0; q < 24; q++) t += (in[base + q] + 3) & ~3;
    int inc = t;
    #pragma unroll
    for (int o = 1; o < 32; o <<= 1) {
        int u = __shfl_up_sync(0xffffffffu, inc, o);
        if (lane >= o) inc += u;
    }
    if (lane == 31) s_w[warp] = inc;
    __syncthreads();
    if (tid == 0) {
        int r = 0;
        #pragma unroll
        for (int w = 0; w < 8; w++) { int x = s_w[w]; s_w[w] = r; r += x; }
        s_w[8] = r;
    }
    __syncthreads();
    int off = s_w[warp] + (inc - t);
    int run = 0;
    #pragma unroll
    for (int q = 0; q < 24; q++) {
        out[base + q] = off + run;
        run += (in[base + q] + 3) & ~3;
    }
    if (tid == 255) out[NN] = s_w[8];
}

// ---------------- count helpers: double-buffered 768-col steps ---------------
__device__ __forceinline__ void cnt_load(const float4* __restrict__ row, int lane,
                                         int it, float4 (&buf)[6]) {
    #pragma unroll
    for (int q = 0; q < 6; q++) buf[q] = row[it * 192 + q * 32 + lane];
}

__device__ __forceinline__ void cnt_proc(float4 (&buf)[6], int lane, int it,
                                         unsigned* __restrict__ bits, int& cnt) {
    unsigned myw = 0;
    #pragma unroll
    for (int q = 0; q < 6; q++) {
        unsigned b0 = __ballot_sync(0xffffffffu, buf[q].x != 0.0f);
        unsigned b1 = __ballot_sync(0xffffffffu, buf[q].y != 0.0f);
        unsigned b2 = __ballot_sync(0xffffffffu, buf[q].z != 0.0f);
        unsigned b3 = __ballot_sync(0xffffffffu, buf[q].w != 0.0f);
        myw = (lane == q * 4 + 0) ? b0 : myw;
        myw = (lane == q * 4 + 1) ? b1 : myw;
        myw = (lane == q * 4 + 2) ? b2 : myw;
        myw = (lane == q * 4 + 3) ? b3 : myw;
        int cb = it * 768 + q * 128 + 4 * lane;
        if (buf[q].x != 0.0f) atomicAdd(&g_col_cnt[cb + 0], 1);
        if (buf[q].y != 0.0f) atomicAdd(&g_col_cnt[cb + 1], 1);
        if (buf[q].z != 0.0f) atomicAdd(&g_col_cnt[cb + 2], 1);
        if (buf[q].w != 0.0f) atomicAdd(&g_col_cnt[cb + 3], 1);
    }
    if (lane < 24) { bits[it * 24 + lane] = myw; cnt += __popc(myw); }
}

// ------- k1: blocks [0,384) x@W GEMM (reg-tiled); [384,1152) count adj -------
__global__ void k1(const float* __restrict__ adj, const float* __restrict__ x,
                   const float* __restrict__ W, const float* __restrict__ a) {
    __shared__ float xs[16][FIN];
    __shared__ float red1[8][4], red2[8][4];
    __shared__ int   s_w[9];
    __shared__ bool  s_last;
    int b = blockIdx.x, tid = threadIdx.x;
    int lane = tid & 31, warp = tid >> 5;

    if (b < GEMM_BLOCKS) {
        int r0 = b * 16;
        const float4* xv = (const float4*)(x + (size_t)r0 * FIN);
        float4* xsv = (float4*)&xs[0][0];
        for (int q = tid; q < 16 * FIN / 4; q += 256) xsv[q] = xv[q];
        __syncthreads();
        int c = tid & 63, g = tid >> 6;
        float acc0 = 0.f, acc1 = 0.f, acc2 = 0.f, acc3 = 0.f;
        const float* x0 = xs[4 * g + 0];
        const float* x1 = xs[4 * g + 1];
        const float* x2 = xs[4 * g + 2];
        const float* x3 = xs[4 * g + 3];
        #pragma unroll 4
        for (int k = 0; k < FIN; k++) {
            float wv = __ldg(&W[k * FOUT + c]);
            acc0 += x0[k] * wv; acc1 += x1[k] * wv;
            acc2 += x2[k] * wv; acc3 += x3[k] * wv;
        }
        g_h[(size_t)(r0 + 4 * g + 0) * FOUT + c] = acc0;
        g_h[(size_t)(r0 + 4 * g + 1) * FOUT + c] = acc1;
        g_h[(size_t)(r0 + 4 * g + 2) * FOUT + c] = acc2;
        g_h[(size_t)(r0 + 4 * g + 3) * FOUT + c] = acc3;
        float a1 = __ldg(&a[c]), a2 = __ldg(&a[64 + c]);
        float v1[4] = {acc0 * a1, acc1 * a1, acc2 * a1, acc3 * a1};
        float v2[4] = {acc0 * a2, acc1 * a2, acc2 * a2, acc3 * a2};
        #pragma unroll
        for (int r = 0; r < 4; r++) {
            #pragma unroll
            for (int o = 16; o; o >>= 1) {
                v1[r] += __shfl_down_sync(0xffffffffu, v1[r], o);
                v2[r] += __shfl_down_sync(0xffffffffu, v2[r], o);
            }
        }
        if (lane == 0) {
            #pragma unroll
            for (int r = 0; r < 4; r++) { red1[warp][r] = v1[r]; red2[warp][r] = v2[r]; }
        }
        __syncthreads();
        if (tid < 16) {
            int gg = tid >> 2, rr = tid & 3;
            g_Wh1[r0 + tid] = red1[2 * gg][rr] + red1[2 * gg + 1][rr];
            g_Wh2[r0 + tid] = red2[2 * gg][rr] + red2[2 * gg + 1][rr];
        }
    } else {
        int w = (b - GEMM_BLOCKS) * 8 + warp;
        const float4* row = (const float4*)(adj + (size_t)w * NN);
        unsigned* bits = g_bits + (size_t)w * NWORDS;
        float4 va[6], vb[6];
        int cnt = 0;
        cnt_load(row, lane, 0, va);
        #pragma unroll
        for (int itp = 0; itp < 4; itp++) {
            cnt_load(row, lane, 2 * itp + 1, vb);
            cnt_proc(va, lane, 2 * itp, bits, cnt);
            if (itp < 3) cnt_load(row, lane, 2 * itp + 2, va);
            cnt_proc(vb, lane, 2 * itp + 1, bits, cnt);
        }
        #pragma unroll
        for (int o = 16; o; o >>= 1) cnt += __shfl_down_sync(0xffffffffu, cnt, o);
        if (lane == 0) g_row_cnt[w] = cnt;
    }

    __threadfence();
    __syncthreads();
    if (tid == 0) s_last = (atomicAdd(&g_ticket, 1u) == (TOT_BLOCKS - 1));
    __syncthreads();
    if (s_last) {
        scan6144_pad(g_row_cnt, g_row_ptr, s_w);
        __syncthreads();
        scan6144_pad(g_col_cnt, g_col_ptr, s_w);
        if (tid == 0) g_ticket = 0;
    }
}

// ------- pass 2: expand permuted bitmask -> padded CSR + CSC + sentinels -----
// word wi (0..191): it = wi/24, rem = wi%24; bit b -> col = it*768+(rem>>2)*128+4*b+(rem&3)
__global__ void k_fill() {
    int w = (blockIdx.x * blockDim.x + threadIdx.x) >> 5;
    int lane = threadIdx.x & 31;
    if (w >= NN) return;
    // csc sentinel padding for column w (real entries filled below by atomics)
    {
        int cbp = g_col_ptr[w];
        int cc = g_col_cnt[w];
        int pad = ((cc + 3) & ~3) - cc;
        if (lane < pad) g_csc_row[cbp + cc + lane] = NN + 1;   // cnt[NN+1] == 0
    }
    const unsigned* bits = g_bits + (size_t)w * NWORDS;
    int base = g_row_ptr[w];
    int off = 0;
    #pragma unroll
    for (int it2 = 0; it2 < 6; it2++) {
        int wi = it2 * 32 + lane;
        unsigned m = bits[wi];
        int c = __popc(m);
        int pre = c;
        #pragma unroll
        for (int o = 1; o < 32; o <<= 1) {
            int v = __shfl_up_sync(0xffffffffu, pre, o);
            if (lane >= o) pre += v;
        }
        int pos = base + off + (pre - c);
        int it = wi / 24;
        int rem = wi - it * 24;
        int cb = it * 768 + (rem >> 2) * 128 + (rem & 3);
        while (m) {
            int bb = __ffs(m) - 1; m &= m - 1;
            int col = cb + 4 * bb;
            g_csr_col[pos++] = col;                  // fixed order (deterministic)
            int cp = atomicAdd(&g_col_fill[col], 1);
            g_csc_row[g_col_ptr[col] + cp] = w;      // unsorted; integer sums only
        }
        off += __shfl_sync(0xffffffffu, pre, 31);
    }
    // csr sentinel padding
    int pad = ((off + 3) & ~3) - off;
    if (lane < pad) g_csr_col[base + off + lane] = NN;          // scratch counter
}

// ---- fused: adj2 (smem atomics, int4 lists) + adj3 + softmax + SpMM + elu ---
__global__ void k_fused(const float* __restrict__ Wsi, const float* __restrict__ Wei,
                        float* __restrict__ out) {
    __shared__ unsigned cnt[NN + 8];      // 24.6 KB; [NN]=csr scratch, [NN+1..7]=zeros
    __shared__ float s_sc[DEGMAX];
    __shared__ int   s_j[DEGMAX];
    __shared__ float s_red[8];
    float* s_part = (float*)cnt;          // union: cnt dead after phase 3

    int i = blockIdx.x, tid = threadIdx.x;
    int warp = tid >> 5, lane = tid & 31;

    // reset accumulators for the NEXT kernel_launch call
    if (i < 24) {
        int t = i * 256 + tid;
        g_col_cnt[t] = 0;
        g_col_fill[t] = 0;
    }

    uint4* cz = (uint4*)cnt;
    for (int q = tid; q < (NN + 8) / 4; q += 256) cz[q] = make_uint4(0, 0, 0, 0);

    int rbp = g_row_ptr[i];
    int deg = g_row_cnt[i];
    for (int e = tid; e < deg; e += 256) s_j[e] = g_csr_col[rbp + e];
    __syncthreads();

    // phase 1: adj2 row i, warp per neighbor k, int4 segment loads
    for (int kk = warp; kk < deg; kk += 8) {
        int k = s_j[kk];
        int kbp = g_row_ptr[k];
        int plen = g_row_ptr[k + 1] - kbp;           // multiple of 4
        for (int t0 = lane * 4; t0 < plen; t0 += 128) {
            int4 cc = *(const int4*)&g_csr_col[kbp + t0];
            atomicAdd(&cnt[cc.x], 1u);
            atomicAdd(&cnt[cc.y], 1u);
            atomicAdd(&cnt[cc.z], 1u);
            atomicAdd(&cnt[cc.w], 1u);
        }
    }
    __syncthreads();

    // phase 2: per-edge score; adj3[i,j] = sum over in-nbrs k of j of cnt[k]
    float aWei = fabsf(*Wei), aWsi = fabsf(*Wsi);
    float wh1 = g_Wh1[i];
    for (int e = warp; e < deg; e += 8) {
        int j = s_j[e];
        int cbp = g_col_ptr[j];
        int plen = g_col_ptr[j + 1] - cbp;           // multiple of 4
        unsigned s3 = 0;
        for (int t0 = lane * 4; t0 < plen; t0 += 128) {
            int4 rr = *(const int4*)&g_csc_row[cbp + t0];
            s3 += cnt[rr.x] + cnt[rr.y] + cnt[rr.z] + cnt[rr.w];
        }
        #pragma unroll
        for (int o = 16; o; o >>= 1) s3 += __shfl_down_sync(0xffffffffu, s3, o);
        if (lane == 0) {
            float aw = 1.0f + (float)cnt[j] + (float)s3;
            float wh = wh1 + g_Wh2[j];
            float lr = wh > 0.f ? wh : ALPHA * wh;
            s_sc[e] = aWei * lr + aWsi * aw;
        }
    }
    __syncthreads();

    // phase 3: softmax over neighbors
    float m = -3.4e38f;
    for (int e = tid; e < deg; e += 256) m = fmaxf(m, s_sc[e]);
    #pragma unroll
    for (int o = 16; o; o >>= 1) m = fmaxf(m, __shfl_xor_sync(0xffffffffu, m, o));
    if (lane == 0) s_red[warp] = m;
    __syncthreads();
    m = s_red[lane & 7];
    #pragma unroll
    for (int o = 4; o; o >>= 1) m = fmaxf(m, __shfl_xor_sync(0xffffffffu, m, o));
    m = __shfl_sync(0xffffffffu, m, 0);
    __syncthreads();

    float sum = 0.f;
    for (int e = tid; e < deg; e += 256) { float p = expf(s_sc[e] - m); s_sc[e] = p; sum += p; }
    #pragma unroll
    for (int o = 16; o; o >>= 1) sum += __shfl_xor_sync(0xffffffffu, sum, o);
    if (lane == 0) s_red[warp] = sum;
    __syncthreads();
    sum = s_red[lane & 7];
    #pragma unroll
    for (int o = 4; o; o >>= 1) sum += __shfl_xor_sync(0xffffffffu, sum, o);
    float inv = 1.0f / __shfl_sync(0xffffffffu, sum, 0);
    __syncthreads();   // cnt region now dead -> reused as s_part

    // phase 4: h_prime[i] = sum_e p_e * h[j_e]; thread = 4 features x 16 groups
    int f4 = tid & 15, g = tid >> 4;
    const float4* h4 = (const float4*)g_h;
    float4 acc = make_float4(0.f, 0.f, 0.f, 0.f);
    if (deg > 0) {
        for (int e = g; e < deg; e += 16) {
            float p = s_sc[e];
            float4 hv = h4[(size_t)s_j[e] * 16 + f4];
            acc.x += p * hv.x; acc.y += p * hv.y;
            acc.z += p * hv.z; acc.w += p * hv.w;
        }
        acc.x *= inv; acc.y *= inv; acc.z *= inv; acc.w *= inv;
    } else {
        for (int j = g; j < NN; j += 16) {
            float4 hv = h4[(size_t)j * 16 + f4];
            acc.x += hv.x; acc.y += hv.y; acc.z += hv.z; acc.w += hv.w;
        }
        acc.x *= (1.0f / NN); acc.y *= (1.0f / NN);
        acc.z *= (1.0f / NN); acc.w *= (1.0f / NN);
    }
    ((float4*)s_part)[g * 16 + f4] = acc;   // s_part[g*64 + f4*4 + c]
    __syncthreads();
    if (tid < 64) {
        float tot = 0.f;
        #pragma unroll
        for (int q = 0; q < 16; q++) tot += s_part[q * 64 + tid];
        out[(size_t)i * FOUT + tid] = tot > 0.f ? tot : expm1f(tot);
    }
}

// ---------------- launch: 3 kernels -------------------------------------------
extern "C" void kernel_launch(void* const* d_in, const int* in_sizes, int n_in,
                              void* d_out, int out_size) {
    const float* x   = (const float*)d_in[0];
    const float* adj = (const float*)d_in[1];
    const float* W   = (const float*)d_in[2];
    const float* a   = (const float*)d_in[3];
    const float* Wsi = (const float*)d_in[4];
    const float* Wei = (const float*)d_in[5];
    float* out = (float*)d_out;

    k1     <<<TOT_BLOCKS, 256>>>(adj, x, W, a);
    k_fill <<<NN / 8, 256>>>();
    k_fused<<<NN, 256>>>(Wsi, Wei, out);
}

// round 12
// speedup vs baseline: 1.0073x; 1.0073x over previous
#include <cuda_runtime.h>
#include <math.h>

#define NN 6144
#define FIN 256
#define FOUT 64
#define ALPHA 0.2f
#define NNZ_MAX (1 << 20)
#define NWORDS (NN / 32)     // 192
#define DEGMAX 192
#define GEMM_BLOCKS (NN / 16)          // 384
#define CNT_BLOCKS  (NN / 8)           // 768
#define TOT_BLOCKS  (GEMM_BLOCKS + CNT_BLOCKS)

// ---------------- scratch (static device globals; zero-initialized) ----------
__device__ float    g_h[NN * FOUT];
__device__ float    g_Wh1[NN];
__device__ float    g_Wh2[NN];
__device__ int      g_row_cnt[NN];
__device__ int      g_col_cnt[NN];    // zeroed by k_fused epilogue for next call
__device__ int      g_row_ptr[NN + 1];
__device__ int      g_col_ptr[NN + 1];
__device__ int      g_col_fill[NN];   // zeroed by k_fused epilogue for next call
__device__ int      g_csr_col[NNZ_MAX];
__device__ int      g_csc_row[NNZ_MAX];
__device__ unsigned g_bits[NN * NWORDS];   // PERMUTED word/bit order (see k_fill)
__device__ unsigned g_ticket;              // reset by the scan block each call

// ---------------- 256-thread exclusive scan over 6144 ints -------------------
__device__ __forceinline__ void scan6144_256(const int* __restrict__ in,
                                             int* __restrict__ out, int* s_w) {
    int tid = threadIdx.x, lane = tid & 31, warp = tid >> 5;
    int base = tid * 24;
    int t = 0;
    #pragma unroll
    for (int q = 0; q < 24; q++) t += in[base + q];
    int inc = t;
    #pragma unroll
    for (int o = 1; o < 32; o <<= 1) {
        int u = __shfl_up_sync(0xffffffffu, inc, o);
        if (lane >= o) inc += u;
    }
    if (lane == 31) s_w[warp] = inc;
    __syncthreads();
    if (tid == 0) {
        int r = 0;
        #pragma unroll
        for (int w = 0; w < 8; w++) { int x = s_w[w]; s_w[w] = r; r += x; }
        s_w[8] = r;
    }
    __syncthreads();
    int off = s_w[warp] + (inc - t);
    int run = 0;
    #pragma unroll
    for (int q = 0; q < 24; q++) { out[base + q] = off + run; run += in[base + q]; }
    if (tid == 255) out[NN] = s_w[8];
}

// ---------------- count helpers: double-buffered 768-col steps ---------------
__device__ __forceinline__ void cnt_load(const float4* __restrict__ row, int lane,
                                         int it, float4 (&buf)[6]) {
    #pragma unroll
    for (int q = 0; q < 6; q++) buf[q] = row[it * 192 + q * 32 + lane];
}

__device__ __forceinline__ void cnt_proc(float4 (&buf)[6], int lane, int it,
                                         unsigned* __restrict__ bits, int& cnt) {
    unsigned myw = 0;
    #pragma unroll
    for (int q = 0; q < 6; q++) {
        unsigned b0 = __ballot_sync(0xffffffffu, buf[q].x != 0.0f);
        unsigned b1 = __ballot_sync(0xffffffffu, buf[q].y != 0.0f);
        unsigned b2 = __ballot_sync(0xffffffffu, buf[q].z != 0.0f);
        unsigned b3 = __ballot_sync(0xffffffffu, buf[q].w != 0.0f);
        myw = (lane == q * 4 + 0) ? b0 : myw;
        myw = (lane == q * 4 + 1) ? b1 : myw;
        myw = (lane == q * 4 + 2) ? b2 : myw;
        myw = (lane == q * 4 + 3) ? b3 : myw;
        int cb = it * 768 + q * 128 + 4 * lane;
        if (buf[q].x != 0.0f) atomicAdd(&g_col_cnt[cb + 0], 1);
        if (buf[q].y != 0.0f) atomicAdd(&g_col_cnt[cb + 1], 1);
        if (buf[q].z != 0.0f) atomicAdd(&g_col_cnt[cb + 2], 1);
        if (buf[q].w != 0.0f) atomicAdd(&g_col_cnt[cb + 3], 1);
    }
    if (lane < 24) { bits[it * 24 + lane] = myw; cnt += __popc(myw); }
}

// ------- k1: blocks [0,384) x@W GEMM (reg-tiled); [384,1152) count adj -------
__global__ void k1(const float* __restrict__ adj, const float* __restrict__ x,
                   const float* __restrict__ W, const float* __restrict__ a) {
    __shared__ float xs[16][FIN];
    __shared__ float red1[8][4], red2[8][4];
    __shared__ int   s_w[9];
    __shared__ bool  s_last;
    int b = blockIdx.x, tid = threadIdx.x;
    int lane = tid & 31, warp = tid >> 5;

    if (b < GEMM_BLOCKS) {
        int r0 = b * 16;
        const float4* xv = (const float4*)(x + (size_t)r0 * FIN);
        float4* xsv = (float4*)&xs[0][0];
        for (int q = tid; q < 16 * FIN / 4; q += 256) xsv[q] = xv[q];
        __syncthreads();
        int c = tid & 63, g = tid >> 6;
        float acc0 = 0.f, acc1 = 0.f, acc2 = 0.f, acc3 = 0.f;
        const float* x0 = xs[4 * g + 0];
        const float* x1 = xs[4 * g + 1];
        const float* x2 = xs[4 * g + 2];
        const float* x3 = xs[4 * g + 3];
        #pragma unroll 4
        for (int k = 0; k < FIN; k++) {
            float wv = __ldg(&W[k * FOUT + c]);
            acc0 += x0[k] * wv; acc1 += x1[k] * wv;
            acc2 += x2[k] * wv; acc3 += x3[k] * wv;
        }
        g_h[(size_t)(r0 + 4 * g + 0) * FOUT + c] = acc0;
        g_h[(size_t)(r0 + 4 * g + 1) * FOUT + c] = acc1;
        g_h[(size_t)(r0 + 4 * g + 2) * FOUT + c] = acc2;
        g_h[(size_t)(r0 + 4 * g + 3) * FOUT + c] = acc3;
        float a1 = __ldg(&a[c]), a2 = __ldg(&a[64 + c]);
        float v1[4] = {acc0 * a1, acc1 * a1, acc2 * a1, acc3 * a1};
        float v2[4] = {acc0 * a2, acc1 * a2, acc2 * a2, acc3 * a2};
        #pragma unroll
        for (int r = 0; r < 4; r++) {
            #pragma unroll
            for (int o = 16; o; o >>= 1) {
                v1[r] += __shfl_down_sync(0xffffffffu, v1[r], o);
                v2[r] += __shfl_down_sync(0xffffffffu, v2[r], o);
            }
        }
        if (lane == 0) {
            #pragma unroll
            for (int r = 0; r < 4; r++) { red1[warp][r] = v1[r]; red2[warp][r] = v2[r]; }
        }
        __syncthreads();
        if (tid < 16) {
            int gg = tid >> 2, rr = tid & 3;
            g_Wh1[r0 + tid] = red1[2 * gg][rr] + red1[2 * gg + 1][rr];
            g_Wh2[r0 + tid] = red2[2 * gg][rr] + red2[2 * gg + 1][rr];
        }
    } else {
        // ---- count: warp/row, software-pipelined double buffer ----
        int w = (b - GEMM_BLOCKS) * 8 + warp;
        const float4* row = (const float4*)(adj + (size_t)w * NN);
        unsigned* bits = g_bits + (size_t)w * NWORDS;
        float4 va[6], vb[6];
        int cnt = 0;
        cnt_load(row, lane, 0, va);
        #pragma unroll
        for (int itp = 0; itp < 4; itp++) {
            cnt_load(row, lane, 2 * itp + 1, vb);
            cnt_proc(va, lane, 2 * itp, bits, cnt);
            if (itp < 3) cnt_load(row, lane, 2 * itp + 2, va);
            cnt_proc(vb, lane, 2 * itp + 1, bits, cnt);
        }
        #pragma unroll
        for (int o = 16; o; o >>= 1) cnt += __shfl_down_sync(0xffffffffu, cnt, o);
        if (lane == 0) g_row_cnt[w] = cnt;
    }

    __threadfence();
    __syncthreads();
    if (tid == 0) s_last = (atomicAdd(&g_ticket, 1u) == (TOT_BLOCKS - 1));
    __syncthreads();
    if (s_last) {
        scan6144_256(g_row_cnt, g_row_ptr, s_w);
        __syncthreads();
        scan6144_256(g_col_cnt, g_col_ptr, s_w);
        if (tid == 0) g_ticket = 0;
    }
}

// ---------------- pass 2: expand permuted bitmask -> CSR + CSC ---------------
// word wi (0..191): it = wi/24, rem = wi%24, q = rem>>2, comp = rem&3
// bit b -> col = it*768 + q*128 + 4*b + comp
__global__ void k_fill() {
    int w = (blockIdx.x * blockDim.x + threadIdx.x) >> 5;
    int lane = threadIdx.x & 31;
    if (w >= NN) return;
    const unsigned* bits = g_bits + (size_t)w * NWORDS;
    int base = g_row_ptr[w];
    int off = 0;
    #pragma unroll
    for (int it2 = 0; it2 < 6; it2++) {
        int wi = it2 * 32 + lane;
        unsigned m = bits[wi];
        int c = __popc(m);
        int pre = c;
        #pragma unroll
        for (int o = 1; o < 32; o <<= 1) {
            int v = __shfl_up_sync(0xffffffffu, pre, o);
            if (lane >= o) pre += v;
        }
        int pos = base + off + (pre - c);
        int it = wi / 24;
        int rem = wi - it * 24;
        int cb = it * 768 + (rem >> 2) * 128 + (rem & 3);
        while (m) {
            int bb = __ffs(m) - 1; m &= m - 1;
            int col = cb + 4 * bb;
            g_csr_col[pos++] = col;                  // fixed order (deterministic)
            int cp = atomicAdd(&g_col_fill[col], 1);
            g_csc_row[g_col_ptr[col] + cp] = w;      // unsorted; integer sums only
        }
        off += __shfl_sync(0xffffffffu, pre, 31);
    }
}

// ---------------- fused: adj2 row (smem atomics) + adj3 + softmax + SpMM ----
__global__ void k_fused(const float* __restrict__ Wsi, const float* __restrict__ Wei,
                        float* __restrict__ out) {
    __shared__ unsigned cnt[NN];          // 24 KB; aliased as s_part after phase 3
    __shared__ float s_sc[DEGMAX];
    __shared__ int   s_j[DEGMAX];
    __shared__ float s_red[8];
    float* s_part = (float*)cnt;          // 4 KB needed; cnt dead after phase 3

    int i = blockIdx.x, tid = threadIdx.x;
    int warp = tid >> 5, lane = tid & 31;

    // reset accumulators for the NEXT kernel_launch call
    if (i < 24) {
        int t = i * 256 + tid;
        g_col_cnt[t] = 0;
        g_col_fill[t] = 0;
    }

    uint4* cz = (uint4*)cnt;
    for (int q = tid; q < NN / 4; q += 256) cz[q] = make_uint4(0, 0, 0, 0);

    int rb = g_row_ptr[i];
    int deg = g_row_ptr[i + 1] - rb;
    for (int e = tid; e < deg; e += 256) s_j[e] = g_csr_col[rb + e];
    __syncthreads();

    // phase 1: adj2 row i (cnt[j] = #paths i->k->j), warp per neighbor k
    for (int kk = warp; kk < deg; kk += 8) {
        int k = s_j[kk];
        int kb = g_row_ptr[k], ke = g_row_ptr[k + 1];
        for (int t = kb + lane; t < ke; t += 32)
            atomicAdd(&cnt[g_csr_col[t]], 1u);
    }
    __syncthreads();

    // phase 2: per-edge score; adj3[i,j] = sum over in-nbrs k of j of cnt[k]
    float aWei = fabsf(*Wei), aWsi = fabsf(*Wsi);
    float wh1 = g_Wh1[i];
    for (int e = warp; e < deg; e += 8) {
        int j = s_j[e];
        int cb = g_col_ptr[j], ce = g_col_ptr[j + 1];
        unsigned s3 = 0;
        for (int t = cb + lane; t < ce; t += 32) s3 += cnt[g_csc_row[t]];
        #pragma unroll
        for (int o = 16; o; o >>= 1) s3 += __shfl_down_sync(0xffffffffu, s3, o);
        if (lane == 0) {
            float aw = 1.0f + (float)cnt[j] + (float)s3;
            float wh = wh1 + g_Wh2[j];
            float lr = wh > 0.f ? wh : ALPHA * wh;
            s_sc[e] = aWei * lr + aWsi * aw;
        }
    }
    __syncthreads();

    // phase 3: softmax over neighbors
    float m = -3.4e38f;
    for (int e = tid; e < deg; e += 256) m = fmaxf(m, s_sc[e]);
    #pragma unroll
    for (int o = 16; o; o >>= 1) m = fmaxf(m, __shfl_xor_sync(0xffffffffu, m, o));
    if (lane == 0) s_red[warp] = m;
    __syncthreads();
    m = s_red[lane & 7];
    #pragma unroll
    for (int o = 4; o; o >>= 1) m = fmaxf(m, __shfl_xor_sync(0xffffffffu, m, o));
    m = __shfl_sync(0xffffffffu, m, 0);
    __syncthreads();

    float sum = 0.f;
    for (int e = tid; e < deg; e += 256) { float p = expf(s_sc[e] - m); s_sc[e] = p; sum += p; }
    #pragma unroll
    for (int o = 16; o; o >>= 1) sum += __shfl_xor_sync(0xffffffffu, sum, o);
    if (lane == 0) s_red[warp] = sum;
    __syncthreads();
    sum = s_red[lane & 7];
    #pragma unroll
    for (int o = 4; o; o >>= 1) sum += __shfl_xor_sync(0xffffffffu, sum, o);
    float inv = 1.0f / __shfl_sync(0xffffffffu, sum, 0);
    __syncthreads();   // cnt now dead -> reuse as s_part

    // phase 4: h_prime[i] = sum_e p_e * h[j_e]; float4 gather
    // thread = (feature quad f4 in 0..15, edge group g in 0..15)
    int f4 = tid & 15, g = tid >> 4;
    const float4* h4 = (const float4*)g_h;
    float4 acc = make_float4(0.f, 0.f, 0.f, 0.f);
    if (deg > 0) {
        for (int e = g; e < deg; e += 16) {
            float p = s_sc[e];
            float4 hv = h4[(size_t)s_j[e] * 16 + f4];
            acc.x += p * hv.x; acc.y += p * hv.y;
            acc.z += p * hv.z; acc.w += p * hv.w;
        }
        acc.x *= inv; acc.y *= inv; acc.z *= inv; acc.w *= inv;
    } else {
        for (int j = g; j < NN; j += 16) {
            float4 hv = h4[(size_t)j * 16 + f4];
            acc.x += hv.x; acc.y += hv.y; acc.z += hv.z; acc.w += hv.w;
        }
        acc.x *= (1.0f / NN); acc.y *= (1.0f / NN);
        acc.z *= (1.0f / NN); acc.w *= (1.0f / NN);
    }
    ((float4*)s_part)[g * 16 + f4] = acc;   // s_part[g*64 + f4*4 + c]
    __syncthreads();
    if (tid < 64) {
        float tot = 0.f;
        #pragma unroll
        for (int q = 0; q < 16; q++) tot += s_part[q * 64 + tid];
        out[(size_t)i * FOUT + tid] = tot > 0.f ? tot : expm1f(tot);
    }
}

// ---------------- launch: 3 kernels -------------------------------------------
extern "C" void kernel_launch(void* const* d_in, const int* in_sizes, int n_in,
                              void* d_out, int out_size) {
    const float* x   = (const float*)d_in[0];
    const float* adj = (const float*)d_in[1];
    const float* W   = (const float*)d_in[2];
    const float* a   = (const float*)d_in[3];
    const float* Wsi = (const float*)d_in[4];
    const float* Wei = (const float*)d_in[5];
    float* out = (float*)d_out;

    k1     <<<TOT_BLOCKS, 256>>>(adj, x, W, a);
    k_fill <<<NN / 8, 256>>>();
    k_fused<<<NN, 256>>>(Wsi, Wei, out);
}

// round 13
// speedup vs baseline: 1.0567x; 1.0491x over previous
#include <cuda_runtime.h>
#include <math.h>

#define NN 6144
#define FIN 256
#define FOUT 64
#define ALPHA 0.2f
#define NNZ_MAX (1 << 20)
#define NWORDS (NN / 32)     // 192
#define DEGMAX 512
#define GEMM_BLOCKS (NN / 16)          // 384
#define CNT_BLOCKS  (NN / 8)           // 768
#define TOT_BLOCKS  (GEMM_BLOCKS + CNT_BLOCKS)

// ---------------- scratch (static device globals; zero-initialized) ----------
__device__ float    g_h[NN * FOUT];
__device__ float    g_Wh1[NN];
__device__ float    g_Wh2[NN];
__device__ int      g_row_cnt[NN];
__device__ int      g_col_cnt[NN];    // zeroed by k_fused epilogue for next call
__device__ int      g_row_ptr[NN + 1];
__device__ int      g_col_ptr[NN + 1];
__device__ int      g_col_fill[NN];   // zeroed by k_fused epilogue for next call
__device__ int      g_csr_col[NNZ_MAX];
__device__ int      g_csc_row[NNZ_MAX];
__device__ unsigned g_bits[NN * NWORDS];   // PERMUTED word/bit order (see k_fill)
__device__ unsigned g_ticket;              // reset by the scan block each call

// ---------------- 256-thread exclusive scan over 6144 ints -------------------
__device__ __forceinline__ void scan6144_256(const int* __restrict__ in,
                                             int* __restrict__ out, int* s_w) {
    int tid = threadIdx.x, lane = tid & 31, warp = tid >> 5;
    int base = tid * 24;
    int t = 0;
    #pragma unroll
    for (int q = 0; q < 24; q++) t += in[base + q];
    int inc = t;
    #pragma unroll
    for (int o = 1; o < 32; o <<= 1) {
        int u = __shfl_up_sync(0xffffffffu, inc, o);
        if (lane >= o) inc += u;
    }
    if (lane == 31) s_w[warp] = inc;
    __syncthreads();
    if (tid == 0) {
        int r = 0;
        #pragma unroll
        for (int w = 0; w < 8; w++) { int x = s_w[w]; s_w[w] = r; r += x; }
        s_w[8] = r;
    }
    __syncthreads();
    int off = s_w[warp] + (inc - t);
    int run = 0;
    #pragma unroll
    for (int q = 0; q < 24; q++) { out[base + q] = off + run; run += in[base + q]; }
    if (tid == 255) out[NN] = s_w[8];
}

// ---------------- count helpers: double-buffered 768-col steps ---------------
__device__ __forceinline__ void cnt_load(const float4* __restrict__ row, int lane,
                                         int it, float4 (&buf)[6]) {
    #pragma unroll
    for (int q = 0; q < 6; q++) buf[q] = row[it * 192 + q * 32 + lane];
}

__device__ __forceinline__ void cnt_proc(float4 (&buf)[6], int lane, int it,
                                         unsigned* __restrict__ bits, int& cnt) {
    unsigned myw = 0;
    #pragma unroll
    for (int q = 0; q < 6; q++) {
        unsigned b0 = __ballot_sync(0xffffffffu, buf[q].x != 0.0f);
        unsigned b1 = __ballot_sync(0xffffffffu, buf[q].y != 0.0f);
        unsigned b2 = __ballot_sync(0xffffffffu, buf[q].z != 0.0f);
        unsigned b3 = __ballot_sync(0xffffffffu, buf[q].w != 0.0f);
        myw = (lane == q * 4 + 0) ? b0 : myw;
        myw = (lane == q * 4 + 1) ? b1 : myw;
        myw = (lane == q * 4 + 2) ? b2 : myw;
        myw = (lane == q * 4 + 3) ? b3 : myw;
        int cb = it * 768 + q * 128 + 4 * lane;
        if (buf[q].x != 0.0f) atomicAdd(&g_col_cnt[cb + 0], 1);
        if (buf[q].y != 0.0f) atomicAdd(&g_col_cnt[cb + 1], 1);
        if (buf[q].z != 0.0f) atomicAdd(&g_col_cnt[cb + 2], 1);
        if (buf[q].w != 0.0f) atomicAdd(&g_col_cnt[cb + 3], 1);
    }
    if (lane < 24) { bits[it * 24 + lane] = myw; cnt += __popc(myw); }
}

// ------- k1: blocks [0,384) x@W GEMM (reg-tiled); [384,1152) count adj -------
__global__ void k1(const float* __restrict__ adj, const float* __restrict__ x,
                   const float* __restrict__ W, const float* __restrict__ a) {
    __shared__ float xs[16][FIN];
    __shared__ float red1[8][4], red2[8][4];
    __shared__ int   s_w[9];
    __shared__ bool  s_last;
    int b = blockIdx.x, tid = threadIdx.x;
    int lane = tid & 31, warp = tid >> 5;

    if (b < GEMM_BLOCKS) {
        int r0 = b * 16;
        const float4* xv = (const float4*)(x + (size_t)r0 * FIN);
        float4* xsv = (float4*)&xs[0][0];
        for (int q = tid; q < 16 * FIN / 4; q += 256) xsv[q] = xv[q];
        __syncthreads();
        int c = tid & 63, g = tid >> 6;
        float acc0 = 0.f, acc1 = 0.f, acc2 = 0.f, acc3 = 0.f;
        const float* x0 = xs[4 * g + 0];
        const float* x1 = xs[4 * g + 1];
        const float* x2 = xs[4 * g + 2];
        const float* x3 = xs[4 * g + 3];
        #pragma unroll 4
        for (int k = 0; k < FIN; k++) {
            float wv = __ldg(&W[k * FOUT + c]);
            acc0 += x0[k] * wv; acc1 += x1[k] * wv;
            acc2 += x2[k] * wv; acc3 += x3[k] * wv;
        }
        g_h[(size_t)(r0 + 4 * g + 0) * FOUT + c] = acc0;
        g_h[(size_t)(r0 + 4 * g + 1) * FOUT + c] = acc1;
        g_h[(size_t)(r0 + 4 * g + 2) * FOUT + c] = acc2;
        g_h[(size_t)(r0 + 4 * g + 3) * FOUT + c] = acc3;
        float a1 = __ldg(&a[c]), a2 = __ldg(&a[64 + c]);
        float v1[4] = {acc0 * a1, acc1 * a1, acc2 * a1, acc3 * a1};
        float v2[4] = {acc0 * a2, acc1 * a2, acc2 * a2, acc3 * a2};
        #pragma unroll
        for (int r = 0; r < 4; r++) {
            #pragma unroll
            for (int o = 16; o; o >>= 1) {
                v1[r] += __shfl_down_sync(0xffffffffu, v1[r], o);
                v2[r] += __shfl_down_sync(0xffffffffu, v2[r], o);
            }
        }
        if (lane == 0) {
            #pragma unroll
            for (int r = 0; r < 4; r++) { red1[warp][r] = v1[r]; red2[warp][r] = v2[r]; }
        }
        __syncthreads();
        if (tid < 16) {
            int gg = tid >> 2, rr = tid & 3;
            g_Wh1[r0 + tid] = red1[2 * gg][rr] + red1[2 * gg + 1][rr];
            g_Wh2[r0 + tid] = red2[2 * gg][rr] + red2[2 * gg + 1][rr];
        }
    } else {
        // ---- count: warp/row, software-pipelined double buffer ----
        int w = (b - GEMM_BLOCKS) * 8 + warp;
        const float4* row = (const float4*)(adj + (size_t)w * NN);
        unsigned* bits = g_bits + (size_t)w * NWORDS;
        float4 va[6], vb[6];
        int cnt = 0;
        cnt_load(row, lane, 0, va);
        #pragma unroll
        for (int itp = 0; itp < 4; itp++) {
            cnt_load(row, lane, 2 * itp + 1, vb);
            cnt_proc(va, lane, 2 * itp, bits, cnt);
            if (itp < 3) cnt_load(row, lane, 2 * itp + 2, va);
            cnt_proc(vb, lane, 2 * itp + 1, bits, cnt);
        }
        #pragma unroll
        for (int o = 16; o; o >>= 1) cnt += __shfl_down_sync(0xffffffffu, cnt, o);
        if (lane == 0) g_row_cnt[w] = cnt;
    }

    __threadfence();
    __syncthreads();
    if (tid == 0) s_last = (atomicAdd(&g_ticket, 1u) == (TOT_BLOCKS - 1));
    __syncthreads();
    if (s_last) {
        scan6144_256(g_row_cnt, g_row_ptr, s_w);
        __syncthreads();
        scan6144_256(g_col_cnt, g_col_ptr, s_w);
        if (tid == 0) g_ticket = 0;
    }
}

// ------- pass 2: expand permuted bitmask -> CSR + CSC, 2 warps per row -------
// word wi (0..191): it = wi/24, rem = wi%24, q = rem>>2, comp = rem&3
// bit b -> col = it*768 + q*128 + 4*b + comp
__global__ void k_fill() {
    int gw = (blockIdx.x * blockDim.x + threadIdx.x) >> 5;   // global warp id
    int lane = threadIdx.x & 31;
    int w = gw >> 1;            // row
    int h = gw & 1;             // half: words [0,96) or [96,192)
    if (w >= NN) return;
    const unsigned* bits = g_bits + (size_t)w * NWORDS;
    int base = g_row_ptr[w];
    if (h) {
        // offset = popcount of first half's 96 words
        int s = __popc(bits[lane]) + __popc(bits[32 + lane]) + __popc(bits[64 + lane]);
        #pragma unroll
        for (int o = 16; o; o >>= 1) s += __shfl_down_sync(0xffffffffu, s, o);
        base += __shfl_sync(0xffffffffu, s, 0);
    }
    int off = 0;
    #pragma unroll
    for (int half_it = 0; half_it < 3; half_it++) {
        int it2 = 3 * h + half_it;
        int wi = it2 * 32 + lane;
        unsigned m = bits[wi];
        int c = __popc(m);
        int pre = c;
        #pragma unroll
        for (int o = 1; o < 32; o <<= 1) {
            int v = __shfl_up_sync(0xffffffffu, pre, o);
            if (lane >= o) pre += v;
        }
        int pos = base + off + (pre - c);
        int it = wi / 24;
        int rem = wi - it * 24;
        int cb = it * 768 + (rem >> 2) * 128 + (rem & 3);
        while (m) {
            int bb = __ffs(m) - 1; m &= m - 1;
            int col = cb + 4 * bb;
            g_csr_col[pos++] = col;                  // fixed order (deterministic)
            int cp = atomicAdd(&g_col_fill[col], 1);
            g_csc_row[g_col_ptr[col] + cp] = w;      // unsorted; integer sums only
        }
        off += __shfl_sync(0xffffffffu, pre, 31);
    }
}

// ---------------- fused: adj2 row (smem atomics) + adj3 + softmax + SpMM ----
__global__ void k_fused(const float* __restrict__ Wsi, const float* __restrict__ Wei,
                        float* __restrict__ out) {
    __shared__ unsigned cnt[NN];          // 24 KB: adj2 row i (exact small ints)
    __shared__ float s_sc[DEGMAX];
    __shared__ int   s_j[DEGMAX];
    __shared__ float s_red[8];
    __shared__ float s_part[256];

    int i = blockIdx.x, tid = threadIdx.x;
    int warp = tid >> 5, lane = tid & 31;

    // reset accumulators for the NEXT kernel_launch call
    if (i < 24) {
        int t = i * 256 + tid;
        g_col_cnt[t] = 0;
        g_col_fill[t] = 0;
    }

    uint4* cz = (uint4*)cnt;
    for (int q = tid; q < NN / 4; q += 256) cz[q] = make_uint4(0, 0, 0, 0);

    int rb = g_row_ptr[i];
    int deg = g_row_ptr[i + 1] - rb;
    for (int e = tid; e < deg; e += 256) s_j[e] = g_csr_col[rb + e];
    __syncthreads();

    // phase 1: adj2 row i (cnt[j] = #paths i->k->j), warp per neighbor k
    for (int kk = warp; kk < deg; kk += 8) {
        int k = s_j[kk];
        int kb = g_row_ptr[k], ke = g_row_ptr[k + 1];
        for (int t = kb + lane; t < ke; t += 32)
            atomicAdd(&cnt[g_csr_col[t]], 1u);
    }
    __syncthreads();

    // phase 2: per-edge score; adj3[i,j] = sum over in-nbrs k of j of cnt[k]
    float aWei = fabsf(*Wei), aWsi = fabsf(*Wsi);
    float wh1 = g_Wh1[i];
    for (int e = warp; e < deg; e += 8) {
        int j = s_j[e];
        int cb = g_col_ptr[j], ce = g_col_ptr[j + 1];
        unsigned s3 = 0;
        for (int t = cb + lane; t < ce; t += 32) s3 += cnt[g_csc_row[t]];
        #pragma unroll
        for (int o = 16; o; o >>= 1) s3 += __shfl_down_sync(0xffffffffu, s3, o);
        if (lane == 0) {
            float aw = 1.0f + (float)cnt[j] + (float)s3;
            float wh = wh1 + g_Wh2[j];
            float lr = wh > 0.f ? wh : ALPHA * wh;
            s_sc[e] = aWei * lr + aWsi * aw;
        }
    }
    __syncthreads();

    // phase 3: softmax over neighbors
    float m = -3.4e38f;
    for (int e = tid; e < deg; e += 256) m = fmaxf(m, s_sc[e]);
    #pragma unroll
    for (int o = 16; o; o >>= 1) m = fmaxf(m, __shfl_xor_sync(0xffffffffu, m, o));
    if (lane == 0) s_red[warp] = m;
    __syncthreads();
    m = s_red[lane & 7];
    #pragma unroll
    for (int o = 4; o; o >>= 1) m = fmaxf(m, __shfl_xor_sync(0xffffffffu, m, o));
    m = __shfl_sync(0xffffffffu, m, 0);
    __syncthreads();

    float sum = 0.f;
    for (int e = tid; e < deg; e += 256) { float p = expf(s_sc[e] - m); s_sc[e] = p; sum += p; }
    #pragma unroll
    for (int o = 16; o; o >>= 1) sum += __shfl_xor_sync(0xffffffffu, sum, o);
    if (lane == 0) s_red[warp] = sum;
    __syncthreads();
    sum = s_red[lane & 7];
    #pragma unroll
    for (int o = 4; o; o >>= 1) sum += __shfl_xor_sync(0xffffffffu, sum, o);
    float inv = 1.0f / __shfl_sync(0xffffffffu, sum, 0);
    __syncthreads();

    // phase 4: h_prime[i] = sum_e p_e * h[j_e]
    int f = tid & 63, g = tid >> 6;
    float acc = 0.f;
    if (deg > 0) {
        for (int e = g; e < deg; e += 4)
            acc += s_sc[e] * g_h[(size_t)s_j[e] * FOUT + f];
        acc *= inv;
    } else {
        for (int j = g; j < NN; j += 4) acc += g_h[(size_t)j * FOUT + f];
        acc *= (1.0f / NN);
    }
    s_part[tid] = acc; __syncthreads();
    if (tid < 64) {
        float tot = s_part[tid] + s_part[64 + tid] + s_part[128 + tid] + s_part[192 + tid];
        out[(size_t)i * FOUT + tid] = tot > 0.f ? tot : expm1f(tot);
    }
}

// ---------------- launch: 3 kernels -------------------------------------------
extern "C" void kernel_launch(void* const* d_in, const int* in_sizes, int n_in,
                              void* d_out, int out_size) {
    const float* x   = (const float*)d_in[0];
    const float* adj = (const float*)d_in[1];
    const float* W   = (const float*)d_in[2];
    const float* a   = (const float*)d_in[3];
    const float* Wsi = (const float*)d_in[4];
    const float* Wei = (const float*)d_in[5];
    float* out = (float*)d_out;

    k1     <<<TOT_BLOCKS, 256>>>(adj, x, W, a);
    k_fill <<<NN / 4, 256>>>();              // 2 warps per row
    k_fused<<<NN, 256>>>(Wsi, Wei, out);
}

// round 14
// speedup vs baseline: 1.1029x; 1.0436x over previous
#include <cuda_runtime.h>
#include <math.h>
#include <stdint.h>

#define NN 6144
#define FIN 256
#define FOUT 64
#define ALPHA 0.2f
#define NNZ_MAX (1 << 20)
#define NWORDS (NN / 32)     // 192
#define DEGMAX 512
#define GEMM_BLOCKS (NN / 16)          // 384
#define CNT_BLOCKS  (NN / 8)           // 768
#define TOT_BLOCKS  (GEMM_BLOCKS + CNT_BLOCKS)
#define STAGE_BYTES 24576              // 8 rows x 768 cols x 4B
#define K1_DSMEM (2 * STAGE_BYTES + 16)

// ---------------- scratch (static device globals; zero-initialized) ----------
__device__ float    g_h[NN * FOUT];
__device__ float    g_Wh1[NN];
__device__ float    g_Wh2[NN];
__device__ int      g_row_cnt[NN];
__device__ int      g_col_cnt[NN];    // zeroed by k_fused epilogue for next call
__device__ int      g_row_ptr[NN + 1];
__device__ int      g_col_ptr[NN + 1];
__device__ int      g_col_fill[NN];   // zeroed by k_fused epilogue for next call
__device__ int      g_csr_col[NNZ_MAX];
__device__ int      g_csc_row[NNZ_MAX];
__device__ unsigned g_bits[NN * NWORDS];   // PERMUTED word/bit order (see k_fill)
__device__ unsigned g_ticket;              // reset by the scan block each call

// ---------------- mbarrier / bulk-async primitives ---------------------------
__device__ __forceinline__ void mbar_init(uint32_t addr, unsigned cnt) {
    asm volatile("mbarrier.init.shared.b64 [%0], %1;" :: "r"(addr), "r"(cnt) : "memory");
}
__device__ __forceinline__ void mbar_expect(uint32_t addr, unsigned tx) {
    asm volatile("mbarrier.arrive.expect_tx.shared.b64 _, [%0], %1;"
                 :: "r"(addr), "r"(tx) : "memory");
}
__device__ __forceinline__ void mbar_wait(uint32_t addr, unsigned parity) {
    asm volatile(
        "{\n\t.reg .pred P;\n\t"
        "WAIT_%=:\n\t"
        "mbarrier.try_wait.parity.shared.b64 P, [%0], %1;\n\t"
        "@P bra.uni DONE_%=;\n\t"
        "bra.uni WAIT_%=;\n\t"
        "DONE_%=:\n\t}"
        :: "r"(addr), "r"(parity) : "memory");
}
__device__ __forceinline__ void bulk_copy(uint32_t smem_dst, const void* gsrc,
                                          unsigned bytes, uint32_t mbar) {
    asm volatile(
        "cp.async.bulk.shared::cluster.global.mbarrier::complete_tx::bytes "
        "[%0], [%1], %2, [%3];"
        :: "r"(smem_dst), "l"(gsrc), "r"(bytes), "r"(mbar) : "memory");
}

// ---------------- 256-thread exclusive scan over 6144 ints -------------------
__device__ __forceinline__ void scan6144_256(const int* __restrict__ in,
                                             int* __restrict__ out, int* s_w) {
    int tid = threadIdx.x, lane = tid & 31, warp = tid >> 5;
    int base = tid * 24;
    int t = 0;
    #pragma unroll
    for (int q = 0; q < 24; q++) t += in[base + q];
    int inc = t;
    #pragma unroll
    for (int o = 1; o < 32; o <<= 1) {
        int u = __shfl_up_sync(0xffffffffu, inc, o);
        if (lane >= o) inc += u;
    }
    if (lane == 31) s_w[warp] = inc;
    __syncthreads();
    if (tid == 0) {
        int r = 0;
        #pragma unroll
        for (int w = 0; w < 8; w++) { int x = s_w[w]; s_w[w] = r; r += x; }
        s_w[8] = r;
    }
    __syncthreads();
    int off = s_w[warp] + (inc - t);
    int run = 0;
    #pragma unroll
    for (int q = 0; q < 24; q++) { out[base + q] = off + run; run += in[base + q]; }
    if (tid == 255) out[NN] = s_w[8];
}

// ------- k1: blocks [0,384) x@W GEMM; [384,1152) bulk-async count ------------
__global__ void k1(const float* __restrict__ adj, const float* __restrict__ x,
                   const float* __restrict__ W, const float* __restrict__ a) {
    extern __shared__ char dsm[];
    __shared__ float red1[8][4], red2[8][4];
    __shared__ int   s_w[9];
    __shared__ bool  s_last;
    int b = blockIdx.x, tid = threadIdx.x;
    int lane = tid & 31, warp = tid >> 5;

    if (b < GEMM_BLOCKS) {
        float (*xs)[FIN] = (float (*)[FIN])dsm;   // 16 KB of the dynamic buffer
        int r0 = b * 16;
        const float4* xv = (const float4*)(x + (size_t)r0 * FIN);
        float4* xsv = (float4*)&xs[0][0];
        for (int q = tid; q < 16 * FIN / 4; q += 256) xsv[q] = xv[q];
        __syncthreads();
        int c = tid & 63, g = tid >> 6;
        float acc0 = 0.f, acc1 = 0.f, acc2 = 0.f, acc3 = 0.f;
        const float* x0 = xs[4 * g + 0];
        const float* x1 = xs[4 * g + 1];
        const float* x2 = xs[4 * g + 2];
        const float* x3 = xs[4 * g + 3];
        #pragma unroll 4
        for (int k = 0; k < FIN; k++) {
            float wv = __ldg(&W[k * FOUT + c]);
            acc0 += x0[k] * wv; acc1 += x1[k] * wv;
            acc2 += x2[k] * wv; acc3 += x3[k] * wv;
        }
        g_h[(size_t)(r0 + 4 * g + 0) * FOUT + c] = acc0;
        g_h[(size_t)(r0 + 4 * g + 1) * FOUT + c] = acc1;
        g_h[(size_t)(r0 + 4 * g + 2) * FOUT + c] = acc2;
        g_h[(size_t)(r0 + 4 * g + 3) * FOUT + c] = acc3;
        float a1 = __ldg(&a[c]), a2 = __ldg(&a[64 + c]);
        float v1[4] = {acc0 * a1, acc1 * a1, acc2 * a1, acc3 * a1};
        float v2[4] = {acc0 * a2, acc1 * a2, acc2 * a2, acc3 * a2};
        #pragma unroll
        for (int r = 0; r < 4; r++) {
            #pragma unroll
            for (int o = 16; o; o >>= 1) {
                v1[r] += __shfl_down_sync(0xffffffffu, v1[r], o);
                v2[r] += __shfl_down_sync(0xffffffffu, v2[r], o);
            }
        }
        if (lane == 0) {
            #pragma unroll
            for (int r = 0; r < 4; r++) { red1[warp][r] = v1[r]; red2[warp][r] = v2[r]; }
        }
        __syncthreads();
        if (tid < 16) {
            int gg = tid >> 2, rr = tid & 3;
            g_Wh1[r0 + tid] = red1[2 * gg][rr] + red1[2 * gg + 1][rr];
            g_Wh2[r0 + tid] = red2[2 * gg][rr] + red2[2 * gg + 1][rr];
        }
    } else {
        // ---- count: 8 rows/block, 2-stage cp.async.bulk pipeline ----
        uint32_t sbase = (uint32_t)__cvta_generic_to_shared(dsm);
        uint32_t mb = sbase + 2 * STAGE_BYTES;
        int row0 = (b - GEMM_BLOCKS) * 8;
        const float* gadj = adj + (size_t)row0 * NN;
        if (tid < 2) mbar_init(mb + 8 * tid, 1);
        __syncthreads();
        if (warp == 0) {   // prologue: issue stages 0 and 1
            if (lane == 0) mbar_expect(mb + 0, STAGE_BYTES);
            __syncwarp();
            if (lane < 8)
                bulk_copy(sbase + lane * 3072, gadj + (size_t)lane * NN, 3072, mb + 0);
            if (lane == 0) mbar_expect(mb + 8, STAGE_BYTES);
            __syncwarp();
            if (lane < 8)
                bulk_copy(sbase + STAGE_BYTES + lane * 3072,
                          gadj + (size_t)lane * NN + 768, 3072, mb + 8);
        }
        unsigned* bits = g_bits + (size_t)(row0 + warp) * NWORDS;
        int cnt = 0;
        #pragma unroll 1
        for (int s = 0; s < 8; s++) {
            int buf = s & 1;
            mbar_wait(mb + 8 * buf, (s >> 1) & 1);
            const float4* src = (const float4*)(dsm + buf * STAGE_BYTES + warp * 3072);
            unsigned myw = 0;
            #pragma unroll
            for (int q = 0; q < 6; q++) {
                float4 v = src[q * 32 + lane];
                unsigned b0 = __ballot_sync(0xffffffffu, v.x != 0.0f);
                unsigned b1 = __ballot_sync(0xffffffffu, v.y != 0.0f);
                unsigned b2 = __ballot_sync(0xffffffffu, v.z != 0.0f);
                unsigned b3 = __ballot_sync(0xffffffffu, v.w != 0.0f);
                myw = (lane == q * 4 + 0) ? b0 : myw;
                myw = (lane == q * 4 + 1) ? b1 : myw;
                myw = (lane == q * 4 + 2) ? b2 : myw;
                myw = (lane == q * 4 + 3) ? b3 : myw;
                int cb = s * 768 + q * 128 + 4 * lane;
                if (v.x != 0.0f) atomicAdd(&g_col_cnt[cb + 0], 1);
                if (v.y != 0.0f) atomicAdd(&g_col_cnt[cb + 1], 1);
                if (v.z != 0.0f) atomicAdd(&g_col_cnt[cb + 2], 1);
                if (v.w != 0.0f) atomicAdd(&g_col_cnt[cb + 3], 1);
            }
            if (lane < 24) { bits[s * 24 + lane] = myw; cnt += __popc(myw); }
            __syncthreads();               // everyone done with buf
            if (s + 2 < 8 && warp == 0) {  // refill buf for stage s+2
                if (lane == 0) mbar_expect(mb + 8 * buf, STAGE_BYTES);
                __syncwarp();
                if (lane < 8)
                    bulk_copy(sbase + buf * STAGE_BYTES + lane * 3072,
                              gadj + (size_t)lane * NN + (s + 2) * 768, 3072,
                              mb + 8 * buf);
            }
        }
        #pragma unroll
        for (int o = 16; o; o >>= 1) cnt += __shfl_down_sync(0xffffffffu, cnt, o);
        if (lane == 0) g_row_cnt[row0 + warp] = cnt;
    }

    __threadfence();
    __syncthreads();
    if (tid == 0) s_last = (atomicAdd(&g_ticket, 1u) == (TOT_BLOCKS - 1));
    __syncthreads();
    if (s_last) {
        scan6144_256(g_row_cnt, g_row_ptr, s_w);
        __syncthreads();
        scan6144_256(g_col_cnt, g_col_ptr, s_w);
        if (tid == 0) g_ticket = 0;
    }
}

// ------- pass 2: expand permuted bitmask -> CSR + CSC, 2 warps per row -------
// word wi (0..191): it = wi/24, rem = wi%24; bit b -> col = it*768+(rem>>2)*128+4*b+(rem&3)
__global__ void k_fill() {
    int gw = (blockIdx.x * blockDim.x + threadIdx.x) >> 5;
    int lane = threadIdx.x & 31;
    int w = gw >> 1;
    int h = gw & 1;
    if (w >= NN) return;
    const unsigned* bits = g_bits + (size_t)w * NWORDS;
    int base = g_row_ptr[w];
    if (h) {
        int s = __popc(bits[lane]) + __popc(bits[32 + lane]) + __popc(bits[64 + lane]);
        #pragma unroll
        for (int o = 16; o; o >>= 1) s += __shfl_down_sync(0xffffffffu, s, o);
        base += __shfl_sync(0xffffffffu, s, 0);
    }
    int off = 0;
    #pragma unroll
    for (int half_it = 0; half_it < 3; half_it++) {
        int it2 = 3 * h + half_it;
        int wi = it2 * 32 + lane;
        unsigned m = bits[wi];
        int c = __popc(m);
        int pre = c;
        #pragma unroll
        for (int o = 1; o < 32; o <<= 1) {
            int v = __shfl_up_sync(0xffffffffu, pre, o);
            if (lane >= o) pre += v;
        }
        int pos = base + off + (pre - c);
        int it = wi / 24;
        int rem = wi - it * 24;
        int cb = it * 768 + (rem >> 2) * 128 + (rem & 3);
        while (m) {
            int bb = __ffs(m) - 1; m &= m - 1;
            int col = cb + 4 * bb;
            g_csr_col[pos++] = col;
            int cp = atomicAdd(&g_col_fill[col], 1);
            g_csc_row[g_col_ptr[col] + cp] = w;
        }
        off += __shfl_sync(0xffffffffu, pre, 31);
    }
}

// ---------------- fused: adj2 row (smem atomics) + adj3 + softmax + SpMM ----
__global__ void k_fused(const float* __restrict__ Wsi, const float* __restrict__ Wei,
                        float* __restrict__ out) {
    __shared__ unsigned cnt[NN];
    __shared__ float s_sc[DEGMAX];
    __shared__ int   s_j[DEGMAX];
    __shared__ float s_red[8];
    __shared__ float s_part[256];

    int i = blockIdx.x, tid = threadIdx.x;
    int warp = tid >> 5, lane = tid & 31;

    if (i < 24) {
        int t = i * 256 + tid;
        g_col_cnt[t] = 0;
        g_col_fill[t] = 0;
    }

    uint4* cz = (uint4*)cnt;
    for (int q = tid; q < NN / 4; q += 256) cz[q] = make_uint4(0, 0, 0, 0);

    int rb = g_row_ptr[i];
    int deg = g_row_ptr[i + 1] - rb;
    for (int e = tid; e < deg; e += 256) s_j[e] = g_csr_col[rb + e];
    __syncthreads();

    for (int kk = warp; kk < deg; kk += 8) {
        int k = s_j[kk];
        int kb = g_row_ptr[k], ke = g_row_ptr[k + 1];
        for (int t = kb + lane; t < ke; t += 32)
            atomicAdd(&cnt[g_csr_col[t]], 1u);
    }
    __syncthreads();

    float aWei = fabsf(*Wei), aWsi = fabsf(*Wsi);
    float wh1 = g_Wh1[i];
    for (int e = warp; e < deg; e += 8) {
        int j = s_j[e];
        int cb = g_col_ptr[j], ce = g_col_ptr[j + 1];
        unsigned s3 = 0;
        for (int t = cb + lane; t < ce; t += 32) s3 += cnt[g_csc_row[t]];
        #pragma unroll
        for (int o = 16; o; o >>= 1) s3 += __shfl_down_sync(0xffffffffu, s3, o);
        if (lane == 0) {
            float aw = 1.0f + (float)cnt[j] + (float)s3;
            float wh = wh1 + g_Wh2[j];
            float lr = wh > 0.f ? wh : ALPHA * wh;
            s_sc[e] = aWei * lr + aWsi * aw;
        }
    }
    __syncthreads();

    float m = -3.4e38f;
    for (int e = tid; e < deg; e += 256) m = fmaxf(m, s_sc[e]);
    #pragma unroll
    for (int o = 16; o; o >>= 1) m = fmaxf(m, __shfl_xor_sync(0xffffffffu, m, o));
    if (lane == 0) s_red[warp] = m;
    __syncthreads();
    m = s_red[lane & 7];
    #pragma unroll
    for (int o = 4; o; o >>= 1) m = fmaxf(m, __shfl_xor_sync(0xffffffffu, m, o));
    m = __shfl_sync(0xffffffffu, m, 0);
    __syncthreads();

    float sum = 0.f;
    for (int e = tid; e < deg; e += 256) { float p = expf(s_sc[e] - m); s_sc[e] = p; sum += p; }
    #pragma unroll
    for (int o = 16; o; o >>= 1) sum += __shfl_xor_sync(0xffffffffu, sum, o);
    if (lane == 0) s_red[warp] = sum;
    __syncthreads();
    sum = s_red[lane & 7];
    #pragma unroll
    for (int o = 4; o; o >>= 1) sum += __shfl_xor_sync(0xffffffffu, sum, o);
    float inv = 1.0f / __shfl_sync(0xffffffffu, sum, 0);
    __syncthreads();

    int f = tid & 63, g = tid >> 6;
    float acc = 0.f;
    if (deg > 0) {
        for (int e = g; e < deg; e += 4)
            acc += s_sc[e] * g_h[(size_t)s_j[e] * FOUT + f];
        acc *= inv;
    } else {
        for (int j = g; j < NN; j += 4) acc += g_h[(size_t)j * FOUT + f];
        acc *= (1.0f / NN);
    }
    s_part[tid] = acc; __syncthreads();
    if (tid < 64) {
        float tot = s_part[tid] + s_part[64 + tid] + s_part[128 + tid] + s_part[192 + tid];
        out[(size_t)i * FOUT + tid] = tot > 0.f ? tot : expm1f(tot);
    }
}

// ---------------- launch: 3 kernels -------------------------------------------
extern "C" void kernel_launch(void* const* d_in, const int* in_sizes, int n_in,
                              void* d_out, int out_size) {
    const float* x   = (const float*)d_in[0];
    const float* adj = (const float*)d_in[1];
    const float* W   = (const float*)d_in[2];
    const float* a   = (const float*)d_in[3];
    const float* Wsi = (const float*)d_in[4];
    const float* Wei = (const float*)d_in[5];
    float* out = (float*)d_out;

    static int cfg_done = 0;
    if (!cfg_done) {
        cudaFuncSetAttribute(k1, cudaFuncAttributeMaxDynamicSharedMemorySize, K1_DSMEM);
        cfg_done = 1;
    }

    k1     <<<TOT_BLOCKS, 256, K1_DSMEM>>>(adj, x, W, a);
    k_fill <<<NN / 4, 256>>>();
    k_fused<<<NN, 256>>>(Wsi, Wei, out);
}